// round 12
// baseline (speedup 1.0000x reference)
#include <cuda_runtime.h>
#include <cuda_bf16.h>
#include <cstdint>
#include <cstddef>

#define B_ 256
#define T_ 256
#define D_ 512
#define H_ 1024
#define C_ 10

// ---------------- device scratch (allocation-free: __device__ globals) ------
__device__ float g_wx[(size_t)B_ * T_ * H_];           // x@Ww + Wb + Ub  [b*T+t][H]
__device__ float g_h[B_ * H_];                         // final h (fp32) for FC
__device__ __nv_bfloat16 g_hs[2][2][B_ * H_];          // bf16 hi/lo of h, parity t&1
__device__ __nv_bfloat16 g_Ut[2][(size_t)H_ * H_];     // U^T splits [n][k]
__device__ __nv_bfloat16 g_Wt[2][(size_t)H_ * D_];     // Ww^T splits [n][k]
__device__ __nv_bfloat16 g_xs[2][(size_t)B_ * T_ * D_];// x splits [m][d]
__device__ unsigned int g_bar[257];                    // step slots 0..255 + reset handshake

// ---------------- helpers ---------------------------------------------------
__device__ __forceinline__ uint32_t smem_u32(const void* p) {
    uint32_t a;
    asm("{ .reg .u64 t; cvta.to.shared.u64 t, %1; cvt.u32.u64 %0, t; }" : "=r"(a) : "l"(p));
    return a;
}
__device__ __forceinline__ void cpa16(uint32_t dst, const void* src) {
    asm volatile("cp.async.cg.shared.global [%0], [%1], 16;" :: "r"(dst), "l"(src) : "memory");
}
#define CP_COMMIT() asm volatile("cp.async.commit_group;" ::: "memory")
#define WG0() asm volatile("cp.async.wait_group 0;" ::: "memory")
#define WG1() asm volatile("cp.async.wait_group 1;" ::: "memory")

__device__ __forceinline__ void ldsm4(uint32_t& r0, uint32_t& r1, uint32_t& r2, uint32_t& r3,
                                      uint32_t addr) {
    asm volatile("ldmatrix.sync.aligned.m8n8.x4.shared.b16 {%0,%1,%2,%3}, [%4];"
                 : "=r"(r0), "=r"(r1), "=r"(r2), "=r"(r3) : "r"(addr));
}
__device__ __forceinline__ void mma16816(float* c, uint32_t a0, uint32_t a1, uint32_t a2,
                                         uint32_t a3, uint32_t b0, uint32_t b1) {
    asm volatile(
        "mma.sync.aligned.m16n8k16.row.col.f32.bf16.bf16.f32 "
        "{%0,%1,%2,%3}, {%4,%5,%6,%7}, {%8,%9}, {%0,%1,%2,%3};"
        : "+f"(c[0]), "+f"(c[1]), "+f"(c[2]), "+f"(c[3])
        : "r"(a0), "r"(a1), "r"(a2), "r"(a3), "r"(b0), "r"(b1));
}
__device__ __forceinline__ void split2(float v, __nv_bfloat16& hi, __nv_bfloat16& lo) {
    hi = __float2bfloat16(v);
    lo = __float2bfloat16(v - __bfloat162float(hi));
}

// ---------------- persistent kernel geometry ---------------------------------
// 128 CTAs = 4 M-tiles(64) x 32 N-tiles(32); 8 warps, warp tile 16x16.
// smem: U^T resident (2 spl x 32 rows x 1024k, rows 2064 B);
//       A ring: 2 stages x (2 spl x 64 rows x 128k, rows 272 B);
//       WX ping-pong: 2 x (64 rows x 32 fp32, rows 144 B).
#define ROWB_U  2064
#define ROWB_A  272
#define PS_U    0
#define PS_USPL 66048            // 32*2064
#define PS_A    132096           // 2*66048
#define PS_ASTG 34816            // 2*17408
#define PS_ASPL 17408            // 64*272
#define PS_WX   201728           // PS_A + 2*34816
#define PS_WXB  9216             // 64*144
#define PS_SMEM 220160           // PS_WX + 2*9216  (215 KB <= 227 KB)

// ---------------- wx kernel geometry ----------------------------------------
#define KC_W   32
#define NCH_W  (D_ / KC_W)
#define ROWB_W 80
#define W_AHI  0
#define W_ALO  10240
#define W_BHI  20480
#define W_BLO  25600
#define W_STAGE 30720
#define W_SMEM (2 * W_STAGE)

// ======================= converter: splits of U^T, Ww^T, x ==================
__global__ void conv_kernel(const float* __restrict__ Uw,
                            const float* __restrict__ Ww,
                            const float* __restrict__ x)
{
    const size_t nu = (size_t)H_ * H_;
    const size_t nw = (size_t)D_ * H_;
    const size_t nx = (size_t)B_ * T_ * D_;
    const size_t total = nu + nw + nx;
    for (size_t i = (size_t)blockIdx.x * blockDim.x + threadIdx.x; i < total;
         i += (size_t)gridDim.x * blockDim.x) {
        __nv_bfloat16 hi, lo;
        if (i < nu) {
            size_t k = i >> 10, n = i & (H_ - 1);
            split2(Uw[k * H_ + n], hi, lo);
            g_Ut[0][n * H_ + k] = hi;
            g_Ut[1][n * H_ + k] = lo;
        } else if (i < nu + nw) {
            size_t j = i - nu;
            size_t k = j >> 10, n = j & (H_ - 1);
            split2(Ww[k * H_ + n], hi, lo);
            g_Wt[0][n * D_ + k] = hi;
            g_Wt[1][n * D_ + k] = lo;
        } else {
            size_t j = i - nu - nw;
            split2(x[j], hi, lo);
            g_xs[0][j] = hi;
            g_xs[1][j] = lo;
        }
    }
}

// ======================= wx = x @ Ww + (Wb+Ub) ==============================
__global__ void __launch_bounds__(256, 1) wx_kernel(
    const float* __restrict__ Wb, const float* __restrict__ Ub)
{
    extern __shared__ char smem[];
    const uint32_t sb = smem_u32(smem);
    const int tid = threadIdx.x;
    const int w = tid >> 5, lane = tid & 31;
    const int m0 = (blockIdx.x >> 4) * 128;
    const int n0 = (blockIdx.x & 15) * 64;
    const int m_off = (w & 3) * 32;
    const int n_off = (w >> 2) * 32;

    float acc[2][4][4];
    #pragma unroll
    for (int a = 0; a < 2; ++a)
        #pragma unroll
        for (int b = 0; b < 4; ++b)
            #pragma unroll
            for (int cc = 0; cc < 4; ++cc) acc[a][b][cc] = 0.f;

#define W_LOAD(buf, k0)                                                        \
    do {                                                                       \
        const uint32_t st = sb + (buf) * W_STAGE;                              \
        _Pragma("unroll")                                                      \
        for (int i = 0; i < 4; ++i) {                                          \
            int u = tid * 4 + i;                                               \
            int s = u >> 9, v = u & 511;                                       \
            int row = v >> 2, kg = v & 3;                                      \
            cpa16(st + s * 10240 + row * ROWB_W + kg * 16,                     \
                  &g_xs[s][(size_t)(m0 + row) * D_ + (k0) + kg * 8]);          \
        }                                                                      \
        _Pragma("unroll")                                                      \
        for (int i = 0; i < 2; ++i) {                                          \
            int u = tid * 2 + i;                                               \
            int s = u >> 8, v = u & 255;                                       \
            int row = v >> 2, kg = v & 3;                                      \
            cpa16(st + W_BHI + s * 5120 + row * ROWB_W + kg * 16,              \
                  &g_Wt[s][(size_t)(n0 + row) * D_ + (k0) + kg * 8]);          \
        }                                                                      \
        CP_COMMIT();                                                           \
    } while (0)

    W_LOAD(0, 0);
    W_LOAD(1, KC_W);

    #pragma unroll 1
    for (int c = 0; c < NCH_W; ++c) {
        if (c + 1 < NCH_W) WG1(); else WG0();
        __syncthreads();
        const uint32_t bb = sb + (c & 1) * W_STAGE;

        #pragma unroll
        for (int kk = 0; kk < KC_W; kk += 16) {
            const uint32_t aoff =
                (uint32_t)((m_off + (lane & 15)) * ROWB_W + (kk + (lane >> 4) * 8) * 2);
            const uint32_t aoff2 = aoff + 16 * ROWB_W;
            const uint32_t boff =
                (uint32_t)((n_off + ((lane >> 4) * 8) + (lane & 7)) * ROWB_W +
                           (kk + ((lane >> 3) & 1) * 8) * 2);
            const uint32_t boff2 = boff + 16 * ROWB_W;

            uint32_t ah[2][4], al[2][4], bh[2][4], bl[2][4];
            ldsm4(ah[0][0], ah[0][1], ah[0][2], ah[0][3], bb + W_AHI + aoff);
            ldsm4(ah[1][0], ah[1][1], ah[1][2], ah[1][3], bb + W_AHI + aoff2);
            ldsm4(al[0][0], al[0][1], al[0][2], al[0][3], bb + W_ALO + aoff);
            ldsm4(al[1][0], al[1][1], al[1][2], al[1][3], bb + W_ALO + aoff2);
            ldsm4(bh[0][0], bh[0][1], bh[0][2], bh[0][3], bb + W_BHI + boff);
            ldsm4(bh[1][0], bh[1][1], bh[1][2], bh[1][3], bb + W_BHI + boff2);
            ldsm4(bl[0][0], bl[0][1], bl[0][2], bl[0][3], bb + W_BLO + boff);
            ldsm4(bl[1][0], bl[1][1], bl[1][2], bl[1][3], bb + W_BLO + boff2);

            #pragma unroll
            for (int mi = 0; mi < 2; ++mi)
                #pragma unroll
                for (int ni = 0; ni < 4; ++ni) {
                    uint32_t p0 = (ni & 2) ? bh[1][(ni & 1) * 2]     : bh[0][(ni & 1) * 2];
                    uint32_t p1 = (ni & 2) ? bh[1][(ni & 1) * 2 + 1] : bh[0][(ni & 1) * 2 + 1];
                    uint32_t q0 = (ni & 2) ? bl[1][(ni & 1) * 2]     : bl[0][(ni & 1) * 2];
                    uint32_t q1 = (ni & 2) ? bl[1][(ni & 1) * 2 + 1] : bl[0][(ni & 1) * 2 + 1];
                    mma16816(acc[mi][ni], ah[mi][0], ah[mi][1], ah[mi][2], ah[mi][3], p0, p1);
                    mma16816(acc[mi][ni], ah[mi][0], ah[mi][1], ah[mi][2], ah[mi][3], q0, q1);
                    mma16816(acc[mi][ni], al[mi][0], al[mi][1], al[mi][2], al[mi][3], p0, p1);
                }
        }
        __syncthreads();
        if (c + 2 < NCH_W) W_LOAD(c & 1, (c + 2) * KC_W);
    }
#undef W_LOAD

    const int g = lane >> 2, qc = (lane & 3) * 2;
    #pragma unroll
    for (int mi = 0; mi < 2; ++mi)
        #pragma unroll
        for (int ni = 0; ni < 4; ++ni) {
            const int col = n0 + n_off + ni * 8 + qc;
            const float bsum0 = Wb[col] + Ub[col];
            const float bsum1 = Wb[col + 1] + Ub[col + 1];
            #pragma unroll
            for (int hf = 0; hf < 2; ++hf) {
                const int row = m0 + m_off + mi * 16 + g + hf * 8;
                float2 r = make_float2(acc[mi][ni][hf * 2] + bsum0,
                                       acc[mi][ni][hf * 2 + 1] + bsum1);
                *(float2*)&g_wx[(size_t)row * H_ + col] = r;
            }
        }
}

// ======================= persistent recurrence + FC =========================
__global__ void __launch_bounds__(256, 1) persist_kernel(
    const float* __restrict__ alpha_p, const float* __restrict__ beta_p,
    const float* __restrict__ fcw, const float* __restrict__ fcb,
    float* __restrict__ out)
{
    extern __shared__ char smem[];
    const uint32_t sb = smem_u32(smem);
    const int tid = threadIdx.x;
    const int w = tid >> 5, lane = tid & 31;
    const int m0 = (blockIdx.x & 3) * 64;
    const int n0 = (blockIdx.x >> 2) * 32;
    const int m_off = (w & 3) * 16;
    const int n_off = (w >> 2) * 16;
    const int g = lane >> 2, qc = (lane & 3) * 2;

    // ---- group: U^T resident tile ----
    #pragma unroll 1
    for (int i = 0; i < 32; ++i) {
        int u = tid * 32 + i;
        int s = u >> 12, v = u & 4095;
        int row = v >> 7, kg = v & 127;
        cpa16(sb + PS_U + s * PS_USPL + row * ROWB_U + kg * 16,
              &g_Ut[s][(size_t)(n0 + row) * H_ + kg * 8]);
    }
    CP_COMMIT();

#define WX_LOAD(buf, tt)                                                       \
    do {                                                                       \
        _Pragma("unroll")                                                      \
        for (int i = 0; i < 2; ++i) {                                          \
            int u = tid * 2 + i;                                               \
            int row = u >> 3, seg = u & 7;                                     \
            cpa16(sb + PS_WX + (buf) * PS_WXB + row * 144 + seg * 16,          \
                  &g_wx[((size_t)(m0 + row) * T_ + (tt)) * H_ + n0 + seg * 4]);\
        }                                                                      \
        CP_COMMIT();                                                           \
    } while (0)

#define A_LOAD(stg, ch)                                                        \
    do {                                                                       \
        const uint32_t st = sb + PS_A + (stg) * PS_ASTG;                       \
        const int k0 = (ch) * 128;                                             \
        _Pragma("unroll")                                                      \
        for (int i = 0; i < 8; ++i) {                                          \
            int u = tid * 8 + i;                                               \
            int s = u >> 10, v = u & 1023;                                     \
            int row = v >> 4, kg = v & 15;                                     \
            cpa16(st + s * PS_ASPL + row * ROWB_A + kg * 16,                   \
                  (s ? hs1 : hs0) + (size_t)(m0 + row) * H_ + k0 + kg * 8);    \
        }                                                                      \
        CP_COMMIT();                                                           \
    } while (0)

    WX_LOAD(0, 0);

    const float alpha = alpha_p[0];
    const float beta  = beta_p[0];
    float h_own[8];
    #pragma unroll
    for (int i = 0; i < 8; ++i) h_own[i] = 0.f;
    float acc[2][4];

#define EPILOGUE(tval)                                                         \
    do {                                                                       \
        const float* wxs = (const float*)(smem + PS_WX + ((tval) & 1) * PS_WXB);\
        _Pragma("unroll")                                                      \
        for (int nb = 0; nb < 2; ++nb) {                                       \
            _Pragma("unroll")                                                  \
            for (int hf = 0; hf < 2; ++hf) {                                   \
                const int row_l = m_off + g + hf * 8;                          \
                const int col_l = n_off + nb * 8 + qc;                         \
                float pre0 = acc[nb][hf * 2]     + wxs[row_l * 36 + col_l];    \
                float pre1 = acc[nb][hf * 2 + 1] + wxs[row_l * 36 + col_l + 1];\
                const int hi = nb * 4 + hf * 2;                                \
                float h0 = alpha * tanhf(pre0) + beta * h_own[hi];             \
                float h1 = alpha * tanhf(pre1) + beta * h_own[hi + 1];         \
                h_own[hi] = h0; h_own[hi + 1] = h1;                            \
                const size_t o = (size_t)(m0 + row_l) * H_ + n0 + col_l;       \
                if ((tval) < 255) {                                            \
                    __nv_bfloat16 a0, b0, a1, b1;                              \
                    split2(h0, a0, b0); split2(h1, a1, b1);                    \
                    __nv_bfloat162 hh = {a0, a1}, ll = {b0, b1};               \
                    *(uint32_t*)&g_hs[((tval) + 1) & 1][0][o] = *(uint32_t*)&hh;\
                    *(uint32_t*)&g_hs[((tval) + 1) & 1][1][o] = *(uint32_t*)&ll;\
                } else {                                                       \
                    *(float2*)&g_h[o] = make_float2(h0, h1);                   \
                }                                                              \
            }                                                                  \
        }                                                                      \
    } while (0)

    // ================= t = 0 : h1 = alpha*tanh(wx_0) =================
    WG0();
    __syncthreads();
    #pragma unroll
    for (int a = 0; a < 2; ++a)
        #pragma unroll
        for (int cc = 0; cc < 4; ++cc) acc[a][cc] = 0.f;
    EPILOGUE(0);
    WX_LOAD(1, 1);           // pending into step 1: {WX1}
    __threadfence();
    __syncthreads();
    if (tid == 0) atomicAdd(&g_bar[0], 1u);

    // ================= t = 1 .. 255 =================
    #pragma unroll 1
    for (int t = 1; t < 256; ++t) {
        if (tid == 0) {
            volatile unsigned int* f = &g_bar[t - 1];
            while (*f < 128u) __nanosleep(32);
        }
        __threadfence();
        __syncthreads();

        const __nv_bfloat16* __restrict__ hs0 = &g_hs[t & 1][0][0];
        const __nv_bfloat16* __restrict__ hs1 = &g_hs[t & 1][1][0];

        #pragma unroll
        for (int a = 0; a < 2; ++a)
            #pragma unroll
            for (int cc = 0; cc < 4; ++cc) acc[a][cc] = 0.f;

        A_LOAD(0, 0);        // pending: {WX(t), A0}

        #pragma unroll 1
        for (int c = 0; c < 8; ++c) {
            __syncthreads();                       // stage-reuse guard
            if (c < 7) A_LOAD((c + 1) & 1, c + 1);
            else {
                const int tn = (t < 255) ? t + 1 : 255;
                WX_LOAD((t + 1) & 1, tn);
            }
            WG1();                                 // uniform ledger: 1 pending
            __syncthreads();                       // cp.async visibility

            const uint32_t bbA = sb + PS_A + (c & 1) * PS_ASTG;
            #pragma unroll
            for (int kk4 = 0; kk4 < 8; ++kk4) {
                const int k_loc = kk4 * 16;
                const int k_abs = c * 128 + k_loc;
                const uint32_t aoff =
                    (uint32_t)((m_off + (lane & 15)) * ROWB_A + (k_loc + (lane >> 4) * 8) * 2);
                const uint32_t boff =
                    (uint32_t)((n_off + ((lane >> 4) * 8) + (lane & 7)) * ROWB_U +
                               (k_abs + ((lane >> 3) & 1) * 8) * 2);

                uint32_t ah[4], al[4], bh[4], bl[4];
                ldsm4(ah[0], ah[1], ah[2], ah[3], bbA + aoff);
                ldsm4(al[0], al[1], al[2], al[3], bbA + PS_ASPL + aoff);
                ldsm4(bh[0], bh[1], bh[2], bh[3], sb + PS_U + boff);
                ldsm4(bl[0], bl[1], bl[2], bl[3], sb + PS_U + PS_USPL + boff);

                mma16816(acc[0], ah[0], ah[1], ah[2], ah[3], bh[0], bh[1]);
                mma16816(acc[1], ah[0], ah[1], ah[2], ah[3], bh[2], bh[3]);
                mma16816(acc[0], ah[0], ah[1], ah[2], ah[3], bl[0], bl[1]);
                mma16816(acc[1], ah[0], ah[1], ah[2], ah[3], bl[2], bl[3]);
                mma16816(acc[0], al[0], al[1], al[2], al[3], bh[0], bh[1]);
                mma16816(acc[1], al[0], al[1], al[2], al[3], bh[2], bh[3]);
            }
        }

        EPILOGUE(t);
        __threadfence();
        __syncthreads();
        if (t < 255 && tid == 0) atomicAdd(&g_bar[t], 1u);
    }

    // ---- final barrier: all g_h visible ----
    if (tid == 0) {
        atomicAdd(&g_bar[255], 1u);
        volatile unsigned int* f = &g_bar[255];
        while (*f < 128u) __nanosleep(32);
    }
    __syncthreads();
    __threadfence();
    if (tid == 0) atomicAdd(&g_bar[256], 1u);   // passed the bar[255] poll

    WG0();   // drain dummy wx group

    // ---- fused FC: rows 2*bid, 2*bid+1 ----
    {
        const int r0 = blockIdx.x * 2;
        for (int p = w; p < 2 * C_; p += 8) {
            const int row = r0 + (p / C_);
            const int col = p % C_;
            float s = 0.f;
            const float* hr = &g_h[(size_t)row * H_];
            for (int k = lane; k < H_; k += 32)
                s += __ldcg(&hr[k]) * fcw[k * C_ + col];
            #pragma unroll
            for (int off = 16; off > 0; off >>= 1)
                s += __shfl_down_sync(0xffffffffu, s, off);
            if (lane == 0) out[row * C_ + col] = s + fcb[col];
        }
    }

    // ---- barrier reset (replay-safe; only after ALL CTAs passed bar[255]) ----
    if (blockIdx.x == 0 && tid == 0) {
        volatile unsigned int* f = &g_bar[256];
        while (*f < 128u) __nanosleep(64);
        for (int i = 0; i < 257; ++i) g_bar[i] = 0u;
        __threadfence();
    }
#undef WX_LOAD
#undef A_LOAD
#undef EPILOGUE
}

// ======================= host ==============================================
extern "C" void kernel_launch(void* const* d_in, const int* in_sizes, int n_in,
                              void* d_out, int out_size)
{
    (void)in_sizes; (void)n_in; (void)out_size;
    const float* x   = (const float*)d_in[0];
    const float* Ww  = (const float*)d_in[1];
    const float* Wb  = (const float*)d_in[2];
    const float* Uw  = (const float*)d_in[3];
    const float* Ub  = (const float*)d_in[4];
    const float* al  = (const float*)d_in[5];
    const float* be  = (const float*)d_in[6];
    const float* fcw = (const float*)d_in[7];
    const float* fcb = (const float*)d_in[8];

    cudaFuncSetAttribute(wx_kernel,      cudaFuncAttributeMaxDynamicSharedMemorySize, W_SMEM);
    cudaFuncSetAttribute(persist_kernel, cudaFuncAttributeMaxDynamicSharedMemorySize, PS_SMEM);

    conv_kernel<<<8192, 256>>>(Uw, Ww, x);
    wx_kernel<<<8192, 256, W_SMEM>>>(Wb, Ub);
    persist_kernel<<<128, 256, PS_SMEM>>>(al, be, fcw, fcb, (float*)d_out);
}

// round 14
// speedup vs baseline: 1.2027x; 1.2027x over previous
#include <cuda_runtime.h>
#include <cuda_fp16.h>
#include <cstdint>
#include <cstddef>

#define B_ 256
#define T_ 256
#define D_ 512
#define H_ 1024
#define C_ 10

// ---------------- device scratch (allocation-free: __device__ globals) ------
__device__ float g_wx[(size_t)B_ * T_ * H_];          // x@Ww + Wb + Ub
__device__ float g_h[B_ * H_];                        // final h (fp32) for FC
__device__ __half g_hs[2][2][B_ * H_];                // fp16 hi/lo of h, parity t&1
__device__ __half g_Ut[(size_t)H_ * H_];              // U^T  hi ONLY [n][k]
__device__ __half g_Wt[(size_t)H_ * D_];              // Ww^T hi ONLY [n][k]
__device__ __half g_xs[2][(size_t)B_ * T_ * D_];      // x hi/lo [m][d]
__device__ unsigned int g_bar[256];                   // grid barrier slots

// ---------------- helpers ---------------------------------------------------
__device__ __forceinline__ uint32_t smem_u32(const void* p) {
    uint32_t a;
    asm("{ .reg .u64 t; cvta.to.shared.u64 t, %1; cvt.u32.u64 %0, t; }" : "=r"(a) : "l"(p));
    return a;
}
__device__ __forceinline__ void cpa16(uint32_t dst, const void* src) {
    asm volatile("cp.async.cg.shared.global [%0], [%1], 16;" :: "r"(dst), "l"(src) : "memory");
}
#define CP_COMMIT() asm volatile("cp.async.commit_group;" ::: "memory")
#define WG0() asm volatile("cp.async.wait_group 0;" ::: "memory")
#define WG1() asm volatile("cp.async.wait_group 1;" ::: "memory")
#define WG2() asm volatile("cp.async.wait_group 2;" ::: "memory")
#define WG3() asm volatile("cp.async.wait_group 3;" ::: "memory")

__device__ __forceinline__ void ldsm4(uint32_t& r0, uint32_t& r1, uint32_t& r2, uint32_t& r3,
                                      uint32_t addr) {
    asm volatile("ldmatrix.sync.aligned.m8n8.x4.shared.b16 {%0,%1,%2,%3}, [%4];"
                 : "=r"(r0), "=r"(r1), "=r"(r2), "=r"(r3) : "r"(addr));
}
__device__ __forceinline__ void mma16816(float* c, uint32_t a0, uint32_t a1, uint32_t a2,
                                         uint32_t a3, uint32_t b0, uint32_t b1) {
    asm volatile(
        "mma.sync.aligned.m16n8k16.row.col.f32.f16.f16.f32 "
        "{%0,%1,%2,%3}, {%4,%5,%6,%7}, {%8,%9}, {%0,%1,%2,%3};"
        : "+f"(c[0]), "+f"(c[1]), "+f"(c[2]), "+f"(c[3])
        : "r"(a0), "r"(a1), "r"(a2), "r"(a3), "r"(b0), "r"(b1));
}
__device__ __forceinline__ void split2h(float v, __half& hi, __half& lo) {
    hi = __float2half(v);
    lo = __float2half(v - __half2float(hi));
}

// ---------------- persistent kernel geometry ---------------------------------
// 128 CTAs = 4 M-tiles(64) x 32 N-tiles(32); 8 warps, warp tile 16x16.
// smem: U^T-hi resident (32 rows x 1024k fp16, rows 2064 B);
//       A ring: 3 stages x (2 spl x 64 rows x 64k, rows 144 B);
//       WX ping-pong: 2 x (64 rows x 32 fp32, rows 144 B).
#define ROWB_U  2064
#define ROWB_A  144
#define PS_U    0
#define PS_A    66048            // 32*2064
#define PS_ASTG 18432            // 2*9216
#define PS_ASPL 9216             // 64*144
#define PS_WX   121344           // PS_A + 3*18432
#define PS_WXB  9216
#define PS_SMEM 139776           // PS_WX + 2*9216

// ---------------- wx kernel geometry ----------------------------------------
// tile 128(M) x 64(N), KC=32; A hi/lo, B hi only.
#define KC_W   32
#define NCH_W  (D_ / KC_W)
#define ROWB_W 80
#define W_AHI  0
#define W_ALO  10240
#define W_BHI  20480
#define W_STAGE 25600
#define W_SMEM (2 * W_STAGE)     // 51200

// ======================= converter: fp16 splits =============================
__global__ void conv_kernel(const float* __restrict__ Uw,
                            const float* __restrict__ Ww,
                            const float* __restrict__ x)
{
    const size_t nu = (size_t)H_ * H_;
    const size_t nw = (size_t)D_ * H_;
    const size_t nx = (size_t)B_ * T_ * D_;
    const size_t total = nu + nw + nx;
    for (size_t i = (size_t)blockIdx.x * blockDim.x + threadIdx.x; i < total;
         i += (size_t)gridDim.x * blockDim.x) {
        if (i < nu) {
            size_t k = i >> 10, n = i & (H_ - 1);
            g_Ut[n * H_ + k] = __float2half(Uw[k * H_ + n]);
        } else if (i < nu + nw) {
            size_t j = i - nu;
            size_t k = j >> 10, n = j & (H_ - 1);
            g_Wt[n * D_ + k] = __float2half(Ww[k * H_ + n]);
        } else {
            size_t j = i - nu - nw;
            __half hi, lo;
            split2h(x[j], hi, lo);
            g_xs[0][j] = hi;
            g_xs[1][j] = lo;
        }
    }
}

// ======================= wx = x @ Ww + (Wb+Ub) ==============================
// 2-pass fp16: xh*Wh + xl*Wh
__global__ void __launch_bounds__(256, 1) wx_kernel(
    const float* __restrict__ Wb, const float* __restrict__ Ub)
{
    extern __shared__ char smem[];
    const uint32_t sb = smem_u32(smem);
    const int tid = threadIdx.x;
    const int w = tid >> 5, lane = tid & 31;
    const int m0 = (blockIdx.x >> 4) * 128;
    const int n0 = (blockIdx.x & 15) * 64;
    const int m_off = (w & 3) * 32;
    const int n_off = (w >> 2) * 32;

    float acc[2][4][4];
    #pragma unroll
    for (int a = 0; a < 2; ++a)
        #pragma unroll
        for (int b = 0; b < 4; ++b)
            #pragma unroll
            for (int cc = 0; cc < 4; ++cc) acc[a][b][cc] = 0.f;

#define W_LOAD(buf, k0)                                                        \
    do {                                                                       \
        const uint32_t st = sb + (buf) * W_STAGE;                              \
        _Pragma("unroll")                                                      \
        for (int i = 0; i < 4; ++i) {                                          \
            int u = tid * 4 + i;                                               \
            int s = u >> 9, v = u & 511;                                       \
            int row = v >> 2, kg = v & 3;                                      \
            cpa16(st + s * 10240 + row * ROWB_W + kg * 16,                     \
                  &g_xs[s][(size_t)(m0 + row) * D_ + (k0) + kg * 8]);          \
        }                                                                      \
        {                                                                      \
            int u = tid;                                                       \
            int row = u >> 2, kg = u & 3;                                      \
            cpa16(st + W_BHI + row * ROWB_W + kg * 16,                         \
                  &g_Wt[(size_t)(n0 + row) * D_ + (k0) + kg * 8]);             \
        }                                                                      \
        CP_COMMIT();                                                           \
    } while (0)

    W_LOAD(0, 0);
    W_LOAD(1, KC_W);

    #pragma unroll 1
    for (int c = 0; c < NCH_W; ++c) {
        if (c + 1 < NCH_W) WG1(); else WG0();
        __syncthreads();
        const uint32_t bb = sb + (c & 1) * W_STAGE;

        #pragma unroll
        for (int kk = 0; kk < KC_W; kk += 16) {
            const uint32_t aoff =
                (uint32_t)((m_off + (lane & 15)) * ROWB_W + (kk + (lane >> 4) * 8) * 2);
            const uint32_t aoff2 = aoff + 16 * ROWB_W;
            const uint32_t boff =
                (uint32_t)((n_off + ((lane >> 4) * 8) + (lane & 7)) * ROWB_W +
                           (kk + ((lane >> 3) & 1) * 8) * 2);
            const uint32_t boff2 = boff + 16 * ROWB_W;

            uint32_t ah[2][4], al[2][4], bh[2][4];
            ldsm4(ah[0][0], ah[0][1], ah[0][2], ah[0][3], bb + W_AHI + aoff);
            ldsm4(ah[1][0], ah[1][1], ah[1][2], ah[1][3], bb + W_AHI + aoff2);
            ldsm4(al[0][0], al[0][1], al[0][2], al[0][3], bb + W_ALO + aoff);
            ldsm4(al[1][0], al[1][1], al[1][2], al[1][3], bb + W_ALO + aoff2);
            ldsm4(bh[0][0], bh[0][1], bh[0][2], bh[0][3], bb + W_BHI + boff);
            ldsm4(bh[1][0], bh[1][1], bh[1][2], bh[1][3], bb + W_BHI + boff2);

            #pragma unroll
            for (int mi = 0; mi < 2; ++mi)
                #pragma unroll
                for (int ni = 0; ni < 4; ++ni) {
                    uint32_t p0 = (ni & 2) ? bh[1][(ni & 1) * 2]     : bh[0][(ni & 1) * 2];
                    uint32_t p1 = (ni & 2) ? bh[1][(ni & 1) * 2 + 1] : bh[0][(ni & 1) * 2 + 1];
                    mma16816(acc[mi][ni], ah[mi][0], ah[mi][1], ah[mi][2], ah[mi][3], p0, p1);
                    mma16816(acc[mi][ni], al[mi][0], al[mi][1], al[mi][2], al[mi][3], p0, p1);
                }
        }
        __syncthreads();
        if (c + 2 < NCH_W) W_LOAD(c & 1, (c + 2) * KC_W);
    }
#undef W_LOAD

    const int g = lane >> 2, qc = (lane & 3) * 2;
    #pragma unroll
    for (int mi = 0; mi < 2; ++mi)
        #pragma unroll
        for (int ni = 0; ni < 4; ++ni) {
            const int col = n0 + n_off + ni * 8 + qc;
            const float bsum0 = Wb[col] + Ub[col];
            const float bsum1 = Wb[col + 1] + Ub[col + 1];
            #pragma unroll
            for (int hf = 0; hf < 2; ++hf) {
                const int row = m0 + m_off + mi * 16 + g + hf * 8;
                float2 r = make_float2(acc[mi][ni][hf * 2] + bsum0,
                                       acc[mi][ni][hf * 2 + 1] + bsum1);
                *(float2*)&g_wx[(size_t)row * H_ + col] = r;
            }
        }
}

// ======================= persistent recurrence kernel =======================
// h_{t+1} = alpha*tanh(h_t @ U + wx_t) + beta*h_t ; 2-pass fp16 (hh + lh).
__global__ void __launch_bounds__(256, 1) persist_kernel(
    const float* __restrict__ alpha_p, const float* __restrict__ beta_p)
{
    extern __shared__ char smem[];
    const uint32_t sb = smem_u32(smem);
    const int tid = threadIdx.x;
    const int w = tid >> 5, lane = tid & 31;
    const int m0 = (blockIdx.x & 3) * 64;
    const int n0 = (blockIdx.x >> 2) * 32;
    const int m_off = (w & 3) * 16;
    const int n_off = (w >> 2) * 16;
    const int g = lane >> 2, qc = (lane & 3) * 2;

    // ---- group 0: U^T-hi resident tile (32 rows x 1024 k fp16) ----
    #pragma unroll 1
    for (int i = 0; i < 16; ++i) {
        int u = tid * 16 + i;
        int row = u >> 7, kg = u & 127;
        cpa16(sb + PS_U + row * ROWB_U + kg * 16,
              &g_Ut[(size_t)(n0 + row) * H_ + kg * 8]);
    }
    CP_COMMIT();

#define WX_LOAD(buf, tt)                                                       \
    do {                                                                       \
        _Pragma("unroll")                                                      \
        for (int i = 0; i < 2; ++i) {                                          \
            int u = tid * 2 + i;                                               \
            int row = u >> 3, seg = u & 7;                                     \
            cpa16(sb + PS_WX + (buf) * PS_WXB + row * ROWB_A + seg * 16,       \
                  &g_wx[((size_t)(m0 + row) * T_ + (tt)) * H_ + n0 + seg * 4]);\
        }                                                                      \
    } while (0)

#define A_LOAD(stg, ch)                                                        \
    do {                                                                       \
        const uint32_t st = sb + PS_A + (stg) * PS_ASTG;                       \
        const int k0 = (ch) * 64;                                              \
        _Pragma("unroll")                                                      \
        for (int i = 0; i < 4; ++i) {                                          \
            int u = tid * 4 + i;                                               \
            int s = u >> 9, v = u & 511;                                       \
            int row = v >> 3, kg = v & 7;                                      \
            cpa16(st + s * PS_ASPL + row * ROWB_A + kg * 16,                   \
                  (s ? hs1 : hs0) + (size_t)(m0 + row) * H_ + k0 + kg * 8);    \
        }                                                                      \
        CP_COMMIT();                                                           \
    } while (0)

    // ---- group 1: wx_0 ----
    WX_LOAD(0, 0);
    CP_COMMIT();

    const float alpha = alpha_p[0];
    const float beta  = beta_p[0];
    float h_own[8];
    #pragma unroll
    for (int i = 0; i < 8; ++i) h_own[i] = 0.f;
    float acc[2][4];

#define EPILOGUE(tval)                                                         \
    do {                                                                       \
        const float* wxs = (const float*)(smem + PS_WX + ((tval) & 1) * PS_WXB);\
        _Pragma("unroll")                                                      \
        for (int nb = 0; nb < 2; ++nb) {                                       \
            _Pragma("unroll")                                                  \
            for (int hf = 0; hf < 2; ++hf) {                                   \
                const int row_l = m_off + g + hf * 8;                          \
                const int col_l = n_off + nb * 8 + qc;                         \
                float pre0 = acc[nb][hf * 2]     + wxs[row_l * 36 + col_l];    \
                float pre1 = acc[nb][hf * 2 + 1] + wxs[row_l * 36 + col_l + 1];\
                const int hi = nb * 4 + hf * 2;                                \
                float h0 = alpha * tanhf(pre0) + beta * h_own[hi];             \
                float h1 = alpha * tanhf(pre1) + beta * h_own[hi + 1];         \
                h_own[hi] = h0; h_own[hi + 1] = h1;                            \
                const size_t o = (size_t)(m0 + row_l) * H_ + n0 + col_l;       \
                if ((tval) < 255) {                                            \
                    __half a0, b0, a1, b1;                                     \
                    split2h(h0, a0, b0); split2h(h1, a1, b1);                  \
                    __half2 hh = __halves2half2(a0, a1);                       \
                    __half2 ll = __halves2half2(b0, b1);                       \
                    *(uint32_t*)&g_hs[((tval) + 1) & 1][0][o] = *(uint32_t*)&hh;\
                    *(uint32_t*)&g_hs[((tval) + 1) & 1][1][o] = *(uint32_t*)&ll;\
                } else {                                                       \
                    *(float2*)&g_h[o] = make_float2(h0, h1);                   \
                }                                                              \
            }                                                                  \
        }                                                                      \
    } while (0)

    // ================= t = 0 : h1 = alpha*tanh(wx_0) =================
    WG0();
    __syncthreads();
    #pragma unroll
    for (int a = 0; a < 2; ++a)
        #pragma unroll
        for (int cc = 0; cc < 4; ++cc) acc[a][cc] = 0.f;
    EPILOGUE(0);
    WX_LOAD(1, 1);           // pending into step 1: {WX1}
    CP_COMMIT();
    __threadfence();
    __syncthreads();
    if (tid == 0) atomicAdd(&g_bar[0], 1u);

    // ================= t = 1 .. 255 =================
    #pragma unroll 1
    for (int t = 1; t < 256; ++t) {
        if (tid == 0) {
            volatile unsigned int* f = &g_bar[t - 1];
            while (*f < 128u) __nanosleep(32);
        }
        __threadfence();
        __syncthreads();

        const __half* __restrict__ hs0 = &g_hs[t & 1][0][0];
        const __half* __restrict__ hs1 = &g_hs[t & 1][1][0];

        #pragma unroll
        for (int a = 0; a < 2; ++a)
            #pragma unroll
            for (int cc = 0; cc < 4; ++cc) acc[a][cc] = 0.f;

        A_LOAD(0, 0);
        A_LOAD(1, 1);

        #pragma unroll 1
        for (int c = 0; c < 16; ++c) {
            __syncthreads();                       // stage-reuse guard
            if (c <= 13) A_LOAD((c + 2) % 3, c + 2);
            if (c == 13) {                         // wx prefetch AFTER last A group
                const int tn = (t < 255) ? t + 1 : 255;
                WX_LOAD((t + 1) & 1, tn);
                CP_COMMIT();
            }
            if (c <= 12) WG2();
            else if (c == 13) WG3();
            else if (c == 14) WG2();
            else WG1();
            __syncthreads();                       // cp.async visibility

            const uint32_t bbA = sb + PS_A + (c % 3) * PS_ASTG;
            #pragma unroll
            for (int kk4 = 0; kk4 < 4; ++kk4) {
                const int k_loc = kk4 * 16;
                const int k_abs = c * 64 + k_loc;
                const uint32_t aoff =
                    (uint32_t)((m_off + (lane & 15)) * ROWB_A + (k_loc + (lane >> 4) * 8) * 2);
                const uint32_t boff =
                    (uint32_t)((n_off + ((lane >> 4) * 8) + (lane & 7)) * ROWB_U +
                               (k_abs + ((lane >> 3) & 1) * 8) * 2);

                uint32_t ah[4], al[4], bh[4];
                ldsm4(ah[0], ah[1], ah[2], ah[3], bbA + aoff);
                ldsm4(al[0], al[1], al[2], al[3], bbA + PS_ASPL + aoff);
                ldsm4(bh[0], bh[1], bh[2], bh[3], sb + PS_U + boff);

                mma16816(acc[0], ah[0], ah[1], ah[2], ah[3], bh[0], bh[1]);
                mma16816(acc[1], ah[0], ah[1], ah[2], ah[3], bh[2], bh[3]);
                mma16816(acc[0], al[0], al[1], al[2], al[3], bh[0], bh[1]);
                mma16816(acc[1], al[0], al[1], al[2], al[3], bh[2], bh[3]);
            }
        }

        EPILOGUE(t);
        __threadfence();
        __syncthreads();
        if (t < 255 && tid == 0) atomicAdd(&g_bar[t], 1u);
    }

    // drain dummy wx group, then exit handshake + barrier reset (replay-safe)
    WG0();
    __syncthreads();
    if (tid == 0) {
        __threadfence();
        atomicAdd(&g_bar[255], 1u);
        if (blockIdx.x == 0) {
            volatile unsigned int* f = &g_bar[255];
            while (*f < 128u) __nanosleep(64);
            for (int i = 0; i < 256; ++i) g_bar[i] = 0u;
            __threadfence();
        }
    }
#undef WX_LOAD
#undef A_LOAD
#undef EPILOGUE
}

// ======================= final FC ==========================================
__global__ void fc_kernel(const float* __restrict__ fcw,
                          const float* __restrict__ fcb,
                          float* __restrict__ out)
{
    const int row  = blockIdx.x;
    const int warp = threadIdx.x >> 5;
    const int lane = threadIdx.x & 31;
    if (warp >= C_) return;
    float s = 0.f;
    const float* hr = &g_h[(size_t)row * H_];
    for (int k = lane; k < H_; k += 32)
        s += hr[k] * fcw[k * C_ + warp];
    #pragma unroll
    for (int off = 16; off > 0; off >>= 1)
        s += __shfl_down_sync(0xffffffffu, s, off);
    if (lane == 0) out[row * C_ + warp] = s + fcb[warp];
}

// ======================= host ==============================================
extern "C" void kernel_launch(void* const* d_in, const int* in_sizes, int n_in,
                              void* d_out, int out_size)
{
    (void)in_sizes; (void)n_in; (void)out_size;
    const float* x   = (const float*)d_in[0];
    const float* Ww  = (const float*)d_in[1];
    const float* Wb  = (const float*)d_in[2];
    const float* Uw  = (const float*)d_in[3];
    const float* Ub  = (const float*)d_in[4];
    const float* al  = (const float*)d_in[5];
    const float* be  = (const float*)d_in[6];
    const float* fcw = (const float*)d_in[7];
    const float* fcb = (const float*)d_in[8];

    cudaFuncSetAttribute(wx_kernel,      cudaFuncAttributeMaxDynamicSharedMemorySize, W_SMEM);
    cudaFuncSetAttribute(persist_kernel, cudaFuncAttributeMaxDynamicSharedMemorySize, PS_SMEM);

    conv_kernel<<<8192, 256>>>(Uw, Ww, x);
    wx_kernel<<<8192, 256, W_SMEM>>>(Wb, Ub);
    persist_kernel<<<128, 256, PS_SMEM>>>(al, be);
    fc_kernel<<<B_, 32 * C_>>>(fcw, fcb, (float*)d_out);
}

// round 15
// speedup vs baseline: 1.6638x; 1.3835x over previous
#include <cuda_runtime.h>
#include <cuda_fp16.h>
#include <cstdint>
#include <cstddef>

#define B_ 256
#define T_ 256
#define D_ 512
#define H_ 1024
#define C_ 10

// ---------------- device scratch (allocation-free: __device__ globals) ------
__device__ float g_wx[(size_t)B_ * T_ * H_];          // x@Ww + Wb + Ub
__device__ float g_h[B_ * H_];                        // final h (fp32) for FC
__device__ __half g_hs[2][2][B_ * H_];                // fp16 hi/lo of h, parity t&1
__device__ __half g_Ut[(size_t)H_ * H_];              // U^T  hi ONLY [n][k]
__device__ __half g_Wt[(size_t)H_ * D_];              // Ww^T hi ONLY [n][k]
__device__ __half g_xs[2][(size_t)B_ * T_ * D_];      // x hi/lo [m][d]
__device__ unsigned int g_bar[8 * 256];               // per-M-group barrier slots
__device__ unsigned int g_done;                       // exit handshake

// ---------------- helpers ---------------------------------------------------
__device__ __forceinline__ uint32_t smem_u32(const void* p) {
    uint32_t a;
    asm("{ .reg .u64 t; cvta.to.shared.u64 t, %1; cvt.u32.u64 %0, t; }" : "=r"(a) : "l"(p));
    return a;
}
__device__ __forceinline__ void cpa16(uint32_t dst, const void* src) {
    asm volatile("cp.async.cg.shared.global [%0], [%1], 16;" :: "r"(dst), "l"(src) : "memory");
}
#define CP_COMMIT() asm volatile("cp.async.commit_group;" ::: "memory")
#define WG0() asm volatile("cp.async.wait_group 0;" ::: "memory")
#define WG1() asm volatile("cp.async.wait_group 1;" ::: "memory")

__device__ __forceinline__ void ldsm4(uint32_t& r0, uint32_t& r1, uint32_t& r2, uint32_t& r3,
                                      uint32_t addr) {
    asm volatile("ldmatrix.sync.aligned.m8n8.x4.shared.b16 {%0,%1,%2,%3}, [%4];"
                 : "=r"(r0), "=r"(r1), "=r"(r2), "=r"(r3) : "r"(addr));
}
__device__ __forceinline__ void mma16816(float* c, uint32_t a0, uint32_t a1, uint32_t a2,
                                         uint32_t a3, uint32_t b0, uint32_t b1) {
    asm volatile(
        "mma.sync.aligned.m16n8k16.row.col.f32.f16.f16.f32 "
        "{%0,%1,%2,%3}, {%4,%5,%6,%7}, {%8,%9}, {%0,%1,%2,%3};"
        : "+f"(c[0]), "+f"(c[1]), "+f"(c[2]), "+f"(c[3])
        : "r"(a0), "r"(a1), "r"(a2), "r"(a3), "r"(b0), "r"(b1));
}
__device__ __forceinline__ void split2h(float v, __half& hi, __half& lo) {
    hi = __float2half(v);
    lo = __float2half(v - __half2float(hi));
}

// ---------------- persistent kernel geometry ---------------------------------
// 128 CTAs = 8 M-groups(32 rows) x 16 N-tiles(64 cols); 8 warps, warp tile 16x16.
// smem: U^T-hi resident (64 rows x 1024k fp16, rows 2064 B) = 132096 B;
//       A ring: 3 stages x (2 spl x 32 rows x 64k, rows 144 B) = 27648 B;
//       WX ping-pong: 2 x (32 rows x 64 fp32, rows 272 B) = 17408 B.
#define ROWB_U  2064
#define ROWB_A  144
#define PS_U    0
#define PS_A    132096
#define PS_ASPL 4608             // 32*144
#define PS_ASTG 9216             // 2*4608
#define PS_WX   159744           // PS_A + 3*9216
#define PS_WXB  8704             // 32*272
#define PS_SMEM 177152           // PS_WX + 2*8704

// ---------------- wx kernel geometry ----------------------------------------
#define KC_W   32
#define NCH_W  (D_ / KC_W)
#define ROWB_W 80
#define W_AHI  0
#define W_ALO  10240
#define W_BHI  20480
#define W_STAGE 25600
#define W_SMEM (2 * W_STAGE)

// ======================= converter: fp16 splits =============================
__global__ void conv_kernel(const float* __restrict__ Uw,
                            const float* __restrict__ Ww,
                            const float* __restrict__ x)
{
    const size_t nu = (size_t)H_ * H_;
    const size_t nw = (size_t)D_ * H_;
    const size_t nx = (size_t)B_ * T_ * D_;
    const size_t total = nu + nw + nx;
    for (size_t i = (size_t)blockIdx.x * blockDim.x + threadIdx.x; i < total;
         i += (size_t)gridDim.x * blockDim.x) {
        if (i < nu) {
            size_t k = i >> 10, n = i & (H_ - 1);
            g_Ut[n * H_ + k] = __float2half(Uw[k * H_ + n]);
        } else if (i < nu + nw) {
            size_t j = i - nu;
            size_t k = j >> 10, n = j & (H_ - 1);
            g_Wt[n * D_ + k] = __float2half(Ww[k * H_ + n]);
        } else {
            size_t j = i - nu - nw;
            __half hi, lo;
            split2h(x[j], hi, lo);
            g_xs[0][j] = hi;
            g_xs[1][j] = lo;
        }
    }
}

// ======================= wx = x @ Ww + (Wb+Ub) ==============================
__global__ void __launch_bounds__(256, 1) wx_kernel(
    const float* __restrict__ Wb, const float* __restrict__ Ub)
{
    extern __shared__ char smem[];
    const uint32_t sb = smem_u32(smem);
    const int tid = threadIdx.x;
    const int w = tid >> 5, lane = tid & 31;
    const int m0 = (blockIdx.x >> 4) * 128;
    const int n0 = (blockIdx.x & 15) * 64;
    const int m_off = (w & 3) * 32;
    const int n_off = (w >> 2) * 32;

    float acc[2][4][4];
    #pragma unroll
    for (int a = 0; a < 2; ++a)
        #pragma unroll
        for (int b = 0; b < 4; ++b)
            #pragma unroll
            for (int cc = 0; cc < 4; ++cc) acc[a][b][cc] = 0.f;

#define W_LOAD(buf, k0)                                                        \
    do {                                                                       \
        const uint32_t st = sb + (buf) * W_STAGE;                              \
        _Pragma("unroll")                                                      \
        for (int i = 0; i < 4; ++i) {                                          \
            int u = tid * 4 + i;                                               \
            int s = u >> 9, v = u & 511;                                       \
            int row = v >> 2, kg = v & 3;                                      \
            cpa16(st + s * 10240 + row * ROWB_W + kg * 16,                     \
                  &g_xs[s][(size_t)(m0 + row) * D_ + (k0) + kg * 8]);          \
        }                                                                      \
        {                                                                      \
            int u = tid;                                                       \
            int row = u >> 2, kg = u & 3;                                      \
            cpa16(st + W_BHI + row * ROWB_W + kg * 16,                         \
                  &g_Wt[(size_t)(n0 + row) * D_ + (k0) + kg * 8]);             \
        }                                                                      \
        CP_COMMIT();                                                           \
    } while (0)

    W_LOAD(0, 0);
    W_LOAD(1, KC_W);

    #pragma unroll 1
    for (int c = 0; c < NCH_W; ++c) {
        if (c + 1 < NCH_W) WG1(); else WG0();
        __syncthreads();
        const uint32_t bb = sb + (c & 1) * W_STAGE;

        #pragma unroll
        for (int kk = 0; kk < KC_W; kk += 16) {
            const uint32_t aoff =
                (uint32_t)((m_off + (lane & 15)) * ROWB_W + (kk + (lane >> 4) * 8) * 2);
            const uint32_t aoff2 = aoff + 16 * ROWB_W;
            const uint32_t boff =
                (uint32_t)((n_off + ((lane >> 4) * 8) + (lane & 7)) * ROWB_W +
                           (kk + ((lane >> 3) & 1) * 8) * 2);
            const uint32_t boff2 = boff + 16 * ROWB_W;

            uint32_t ah[2][4], al[2][4], bh[2][4];
            ldsm4(ah[0][0], ah[0][1], ah[0][2], ah[0][3], bb + W_AHI + aoff);
            ldsm4(ah[1][0], ah[1][1], ah[1][2], ah[1][3], bb + W_AHI + aoff2);
            ldsm4(al[0][0], al[0][1], al[0][2], al[0][3], bb + W_ALO + aoff);
            ldsm4(al[1][0], al[1][1], al[1][2], al[1][3], bb + W_ALO + aoff2);
            ldsm4(bh[0][0], bh[0][1], bh[0][2], bh[0][3], bb + W_BHI + boff);
            ldsm4(bh[1][0], bh[1][1], bh[1][2], bh[1][3], bb + W_BHI + boff2);

            #pragma unroll
            for (int mi = 0; mi < 2; ++mi)
                #pragma unroll
                for (int ni = 0; ni < 4; ++ni) {
                    uint32_t p0 = (ni & 2) ? bh[1][(ni & 1) * 2]     : bh[0][(ni & 1) * 2];
                    uint32_t p1 = (ni & 2) ? bh[1][(ni & 1) * 2 + 1] : bh[0][(ni & 1) * 2 + 1];
                    mma16816(acc[mi][ni], ah[mi][0], ah[mi][1], ah[mi][2], ah[mi][3], p0, p1);
                    mma16816(acc[mi][ni], al[mi][0], al[mi][1], al[mi][2], al[mi][3], p0, p1);
                }
        }
        __syncthreads();
        if (c + 2 < NCH_W) W_LOAD(c & 1, (c + 2) * KC_W);
    }
#undef W_LOAD

    const int g = lane >> 2, qc = (lane & 3) * 2;
    #pragma unroll
    for (int mi = 0; mi < 2; ++mi)
        #pragma unroll
        for (int ni = 0; ni < 4; ++ni) {
            const int col = n0 + n_off + ni * 8 + qc;
            const float bsum0 = Wb[col] + Ub[col];
            const float bsum1 = Wb[col + 1] + Ub[col + 1];
            #pragma unroll
            for (int hf = 0; hf < 2; ++hf) {
                const int row = m0 + m_off + mi * 16 + g + hf * 8;
                float2 r = make_float2(acc[mi][ni][hf * 2] + bsum0,
                                       acc[mi][ni][hf * 2 + 1] + bsum1);
                *(float2*)&g_wx[(size_t)row * H_ + col] = r;
            }
        }
}

// ======================= persistent recurrence kernel =======================
// h_{t+1} = alpha*tanh(h_t @ U + wx_t) + beta*h_t ; 2-pass fp16.
// 8 independent M-group barriers (16 CTAs each). Single sync per chunk.
__global__ void __launch_bounds__(256, 1) persist_kernel(
    const float* __restrict__ alpha_p, const float* __restrict__ beta_p)
{
    extern __shared__ char smem[];
    const uint32_t sb = smem_u32(smem);
    const int tid = threadIdx.x;
    const int w = tid >> 5, lane = tid & 31;
    const int mg = blockIdx.x >> 4;          // M group 0..7
    const int m0 = mg * 32;
    const int n0 = (blockIdx.x & 15) * 64;
    const int m_half = (w & 1) * 16;
    const int n_w    = (w >> 1) * 16;
    const int g = lane >> 2, qc = (lane & 3) * 2;
    unsigned int* const bar = &g_bar[mg * 256];

    // ---- group 0: U^T-hi resident tile (64 rows x 1024 k fp16) ----
    #pragma unroll 1
    for (int i = 0; i < 32; ++i) {
        int u = tid * 32 + i;
        int row = u >> 7, kg = u & 127;
        cpa16(sb + PS_U + row * ROWB_U + kg * 16,
              &g_Ut[(size_t)(n0 + row) * H_ + kg * 8]);
    }
    CP_COMMIT();

#define WX_LOAD(buf, tt)                                                       \
    do {                                                                       \
        _Pragma("unroll")                                                      \
        for (int i = 0; i < 2; ++i) {                                          \
            int u = tid * 2 + i;                                               \
            int row = u >> 4, seg = u & 15;                                    \
            cpa16(sb + PS_WX + (buf) * PS_WXB + row * 272 + seg * 16,          \
                  &g_wx[((size_t)(m0 + row) * T_ + (tt)) * H_ + n0 + seg * 4]);\
        }                                                                      \
        CP_COMMIT();                                                           \
    } while (0)

#define A_LOAD(stg, ch)                                                        \
    do {                                                                       \
        const uint32_t st = sb + PS_A + (stg) * PS_ASTG;                       \
        const int k0 = (ch) * 64;                                              \
        _Pragma("unroll")                                                      \
        for (int i = 0; i < 2; ++i) {                                          \
            int u = tid * 2 + i;                                               \
            int s = u >> 8, v = u & 255;                                       \
            int row = v >> 3, kg = v & 7;                                      \
            cpa16(st + s * PS_ASPL + row * ROWB_A + kg * 16,                   \
                  (s ? hs1 : hs0) + (size_t)(m0 + row) * H_ + k0 + kg * 8);    \
        }                                                                      \
        CP_COMMIT();                                                           \
    } while (0)

    WX_LOAD(0, 0);

    const float alpha = alpha_p[0];
    const float beta  = beta_p[0];
    float h_own[8];
    #pragma unroll
    for (int i = 0; i < 8; ++i) h_own[i] = 0.f;
    float acc[2][4];

#define EPILOGUE(tval)                                                         \
    do {                                                                       \
        const float* wxs = (const float*)(smem + PS_WX + ((tval) & 1) * PS_WXB);\
        _Pragma("unroll")                                                      \
        for (int nb = 0; nb < 2; ++nb) {                                       \
            _Pragma("unroll")                                                  \
            for (int hf = 0; hf < 2; ++hf) {                                   \
                const int row_l = m_half + g + hf * 8;                         \
                const int col_l = n_w + nb * 8 + qc;                           \
                float pre0 = acc[nb][hf * 2]     + wxs[row_l * 68 + col_l];    \
                float pre1 = acc[nb][hf * 2 + 1] + wxs[row_l * 68 + col_l + 1];\
                const int hi = nb * 4 + hf * 2;                                \
                float h0 = alpha * tanhf(pre0) + beta * h_own[hi];             \
                float h1 = alpha * tanhf(pre1) + beta * h_own[hi + 1];         \
                h_own[hi] = h0; h_own[hi + 1] = h1;                            \
                const size_t o = (size_t)(m0 + row_l) * H_ + n0 + col_l;       \
                if ((tval) < 255) {                                            \
                    __half a0, b0, a1, b1;                                     \
                    split2h(h0, a0, b0); split2h(h1, a1, b1);                  \
                    __half2 hh = __halves2half2(a0, a1);                       \
                    __half2 ll = __halves2half2(b0, b1);                       \
                    *(uint32_t*)&g_hs[((tval) + 1) & 1][0][o] = *(uint32_t*)&hh;\
                    *(uint32_t*)&g_hs[((tval) + 1) & 1][1][o] = *(uint32_t*)&ll;\
                } else {                                                       \
                    *(float2*)&g_h[o] = make_float2(h0, h1);                   \
                }                                                              \
            }                                                                  \
        }                                                                      \
    } while (0)

    // ================= t = 0 : h1 = alpha*tanh(wx_0) =================
    WG0();                       // U + WX0 resident
    __syncthreads();
    #pragma unroll
    for (int a = 0; a < 2; ++a)
        #pragma unroll
        for (int cc = 0; cc < 4; ++cc) acc[a][cc] = 0.f;
    EPILOGUE(0);
    WX_LOAD(1, 1);               // pending into step 1: {WX1}
    __threadfence();
    __syncthreads();
    if (tid == 0) atomicAdd(&bar[0], 1u);

    // ================= t = 1 .. 255 =================
    #pragma unroll 1
    for (int t = 1; t < 256; ++t) {
        if (tid == 0) {
            volatile unsigned int* f = &bar[t - 1];
            while (*f < 16u) __nanosleep(32);
        }
        __threadfence();
        __syncthreads();

        const __half* __restrict__ hs0 = &g_hs[t & 1][0][0];
        const __half* __restrict__ hs1 = &g_hs[t & 1][1][0];

        #pragma unroll
        for (int a = 0; a < 2; ++a)
            #pragma unroll
            for (int cc = 0; cc < 4; ++cc) acc[a][cc] = 0.f;

        A_LOAD(0, 0);            // pending: {WX(t), A0, A1}
        A_LOAD(1, 1);

        #pragma unroll 1
        for (int c = 0; c < 16; ++c) {
            WG1();               // uniform: leaves exactly 1 group pending
            __syncthreads();     // visibility + all threads past chunk c-1
            if (c < 14) A_LOAD((c + 2) % 3, c + 2);
            else if (c == 14) {
                const int tn = (t < 255) ? t + 1 : 255;
                WX_LOAD((t + 1) & 1, tn);
            }

            const uint32_t bbA = sb + PS_A + (c % 3) * PS_ASTG;
            #pragma unroll
            for (int kk4 = 0; kk4 < 4; ++kk4) {
                const int k_loc = kk4 * 16;
                const int k_abs = c * 64 + k_loc;
                const uint32_t aoff =
                    (uint32_t)((m_half + (lane & 15)) * ROWB_A + (k_loc + (lane >> 4) * 8) * 2);
                const uint32_t boff =
                    (uint32_t)((n_w + ((lane >> 4) * 8) + (lane & 7)) * ROWB_U +
                               (k_abs + ((lane >> 3) & 1) * 8) * 2);

                uint32_t ah[4], al[4], bh[4];
                ldsm4(ah[0], ah[1], ah[2], ah[3], bbA + aoff);
                ldsm4(al[0], al[1], al[2], al[3], bbA + PS_ASPL + aoff);
                ldsm4(bh[0], bh[1], bh[2], bh[3], sb + PS_U + boff);

                mma16816(acc[0], ah[0], ah[1], ah[2], ah[3], bh[0], bh[1]);
                mma16816(acc[1], ah[0], ah[1], ah[2], ah[3], bh[2], bh[3]);
                mma16816(acc[0], al[0], al[1], al[2], al[3], bh[0], bh[1]);
                mma16816(acc[1], al[0], al[1], al[2], al[3], bh[2], bh[3]);
            }
        }

        EPILOGUE(t);
        __threadfence();
        __syncthreads();
        if (t < 255 && tid == 0) atomicAdd(&bar[t], 1u);
    }

    // drain dummy wx group; exit handshake + barrier reset (replay-safe)
    WG0();
    __syncthreads();
    if (tid == 0) {
        __threadfence();
        atomicAdd(&g_done, 1u);
    }
    if (blockIdx.x == 0) {
        if (tid == 0) {
            volatile unsigned int* f = &g_done;
            while (*f < 128u) __nanosleep(64);
            __threadfence();
        }
        __syncthreads();
        for (int i = tid; i < 8 * 256; i += 256) g_bar[i] = 0u;
        if (tid == 0) { g_done = 0u; __threadfence(); }
    }
#undef WX_LOAD
#undef A_LOAD
#undef EPILOGUE
}

// ======================= final FC ==========================================
__global__ void fc_kernel(const float* __restrict__ fcw,
                          const float* __restrict__ fcb,
                          float* __restrict__ out)
{
    const int row  = blockIdx.x;
    const int warp = threadIdx.x >> 5;
    const int lane = threadIdx.x & 31;
    if (warp >= C_) return;
    float s = 0.f;
    const float* hr = &g_h[(size_t)row * H_];
    for (int k = lane; k < H_; k += 32)
        s += hr[k] * fcw[k * C_ + warp];
    #pragma unroll
    for (int off = 16; off > 0; off >>= 1)
        s += __shfl_down_sync(0xffffffffu, s, off);
    if (lane == 0) out[row * C_ + warp] = s + fcb[warp];
}

// ======================= host ==============================================
extern "C" void kernel_launch(void* const* d_in, const int* in_sizes, int n_in,
                              void* d_out, int out_size)
{
    (void)in_sizes; (void)n_in; (void)out_size;
    const float* x   = (const float*)d_in[0];
    const float* Ww  = (const float*)d_in[1];
    const float* Wb  = (const float*)d_in[2];
    const float* Uw  = (const float*)d_in[3];
    const float* Ub  = (const float*)d_in[4];
    const float* al  = (const float*)d_in[5];
    const float* be  = (const float*)d_in[6];
    const float* fcw = (const float*)d_in[7];
    const float* fcb = (const float*)d_in[8];

    cudaFuncSetAttribute(wx_kernel,      cudaFuncAttributeMaxDynamicSharedMemorySize, W_SMEM);
    cudaFuncSetAttribute(persist_kernel, cudaFuncAttributeMaxDynamicSharedMemorySize, PS_SMEM);

    conv_kernel<<<8192, 256>>>(Uw, Ww, x);
    wx_kernel<<<8192, 256, W_SMEM>>>(Wb, Ub);
    persist_kernel<<<128, 256, PS_SMEM>>>(al, be);
    fc_kernel<<<B_, 32 * C_>>>(fcw, fcb, (float*)d_out);
}